// round 16
// baseline (speedup 1.0000x reference)
#include <cuda_runtime.h>
#include <cstdint>

// ColumnConsistencyLoss — bulk-streaming rewrite.
// loss = mean over columns with n>1 of (q_c - |s_c|^2/n_c) / (n_c * C)
// Insight (R14 post-mortem): every LDG/LDGSTS/prefetch path is capped at
// ~64 in-flight lines per SM (~8KB) -> ~1.5TB/s on DRAM-latency loads.
// The bulk engine has its own deep queue. So: each CTA streams its CONTIGUOUS
// token slice via sequential 64KB cp.async.bulk into a 3-stage smem ring
// (~192KB in flight/SM), softmaxes in-place in smem, owner-warps route rows
// to per-column register accumulators, partials reduced after a grid barrier.

#define C_DIM     128
#define NCTA      128
#define NWARPS    32
#define NTHREADS  (NWARPS * 32)   // 1024
#define TILE_T    128             // tokens per tile
#define TILE_B    (TILE_T * 512)  // 64KB per tile
#define NSTAGE    3               // ring depth -> 192KB dynamic smem
#define CHUNK     16384           // bulk chunk size
#define DET_WORDS 2048
#define META_W    1024            // supports per-CTA slice <= 4096 tokens

__device__ float    g_S[(size_t)C_DIM * NCTA * C_DIM];  // [col][cta][dim], 8MB
__device__ float    g_Q[C_DIM * NCTA];
__device__ float    g_N[C_DIM * NCTA];
__device__ float    g_total;
__device__ int      g_cnt;
__device__ unsigned g_done;
__device__ unsigned g_bar;

__device__ __forceinline__ float warp_sum(float x) {
    x += __shfl_xor_sync(0xffffffffu, x, 16);
    x += __shfl_xor_sync(0xffffffffu, x, 8);
    x += __shfl_xor_sync(0xffffffffu, x, 4);
    x += __shfl_xor_sync(0xffffffffu, x, 2);
    x += __shfl_xor_sync(0xffffffffu, x, 1);
    return x;
}
__device__ __forceinline__ void mbar_init(uint32_t a, unsigned cnt) {
    asm volatile("mbarrier.init.shared.b64 [%0], %1;" :: "r"(a), "r"(cnt) : "memory");
}
__device__ __forceinline__ void mbar_expect_tx(uint32_t a, unsigned bytes) {
    asm volatile("mbarrier.arrive.expect_tx.shared.b64 _, [%0], %1;"
                 :: "r"(a), "r"(bytes) : "memory");
}
__device__ __forceinline__ void mbar_wait(uint32_t a, unsigned parity) {
    unsigned done;
    asm volatile("{\n\t.reg .pred p;\n\t"
                 "mbarrier.try_wait.parity.acquire.cta.shared::cta.b64 p, [%1], %2;\n\t"
                 "selp.b32 %0, 1, 0, p;\n\t}"
                 : "=r"(done) : "r"(a), "r"(parity) : "memory");
    while (!done) {
        asm volatile("{\n\t.reg .pred p;\n\t"
                     "mbarrier.try_wait.parity.acquire.cta.shared::cta.b64 p, [%1], %2, 0x989680;\n\t"
                     "selp.b32 %0, 1, 0, p;\n\t}"
                     : "=r"(done) : "r"(a), "r"(parity) : "memory");
    }
}
__device__ __forceinline__ void bulk_cp(uint32_t dst, const void* src,
                                        unsigned bytes, uint32_t mbar) {
    asm volatile("cp.async.bulk.shared::cluster.global.mbarrier::complete_tx::bytes"
                 " [%0], [%1], %2, [%3];"
                 :: "r"(dst), "l"(src), "r"(bytes), "r"(mbar) : "memory");
}

__global__ void __launch_bounds__(NTHREADS, 1)
fused_kernel(const float* __restrict__ logits, const int* __restrict__ seg,
             const void* __restrict__ mask, float* __restrict__ out, int n)
{
    extern __shared__ float ring[];             // NSTAGE * TILE_B = 192KB
    __shared__ unsigned s_meta[META_W];         // (seg|valid<<7) per token
    __shared__ float    s_part[8 * C_DIM];
    __shared__ float    s_red[4], s_redq[4], s_redn[4];
    __shared__ uint64_t s_mbar[NSTAGE];

    int tid  = threadIdx.x;
    int lane = tid & 31;
    int warp = tid >> 5;
    int bid  = blockIdx.x;
    int c    = bid;

    uint32_t mb_base = (uint32_t)__cvta_generic_to_shared(s_mbar);
    uint32_t rg_base = (uint32_t)__cvta_generic_to_shared(ring);

    // Per-CTA contiguous slice, whole tiles.
    int per    = (n + NCTA - 1) / NCTA;
    int ntiles = (per + TILE_T - 1) / TILE_T;
    per = ntiles * TILE_T;
    size_t start = (size_t)bid * per;

    if (tid == 0) {
        #pragma unroll
        for (int i = 0; i < NSTAGE; i++) mbar_init(mb_base + i * 8, 1);
    }
    __syncthreads();

    // Pre-issue first NSTAGE tiles (overlaps with detection + meta build).
    if (tid == 0) {
        for (int t = 0; t < NSTAGE && t < ntiles; t++) {
            int r = t;
            long long gtok = (long long)start + (long long)t * TILE_T;
            long long rows = (long long)n - gtok;
            if (rows > TILE_T) rows = TILE_T;
            if (rows > 0) {
                unsigned bytes = (unsigned)rows * 512u;
                mbar_expect_tx(mb_base + r * 8, bytes);
                const char* src = (const char*)logits + gtok * 512;
                for (unsigned off = 0; off < bytes; off += CHUNK) {
                    unsigned sz = bytes - off; if (sz > CHUNK) sz = CHUNK;
                    bulk_cp(rg_base + r * TILE_B + off, src + off, sz, mb_base + r * 8);
                }
            } else {
                mbar_expect_tx(mb_base + r * 8, 0);
            }
        }
    }

    // ---- Phase 0: redundant local mask-dtype detection. ----
    const unsigned* mwp = (const unsigned*)mask;
    int detw = min(DET_WORDS, n >> 2);
    int f_gt1 = 0, f_off = 0;
    for (int i = tid; i < detw; i += NTHREADS) {
        unsigned w = mwp[i];
        f_gt1 |= ((w & 0xFEFEFEFEu) != 0u);   // byte >= 2      -> float32 mask
        f_off |= ((w & 0xFFFFFF00u) != 0u);   // nonzero b1..b3 -> uint8 mask
    }
    int m_gt1 = __syncthreads_or(f_gt1);
    int m_off = __syncthreads_or(f_off);

    // ---- Phase 1: CTA-local meta (seg|valid<<7 per token of my slice). ----
    {
        const int4*     sg4 = (const int4*)seg;
        const float4*   mf4 = (const float4*)mask;
        const unsigned* mu  = (const unsigned*)mask;
        const int4*     mi4 = (const int4*)mask;
        int nw4 = per >> 2;
        for (int i = tid; i < nw4; i += NTHREADS) {
            size_t gw = (start >> 2) + i;
            size_t gt = start + 4 * (size_t)i;
            unsigned mword;
            if (gt + 3 < (size_t)n) {
                int4 s4 = sg4[gw];
                unsigned vm;
                if (m_gt1) {
                    float4 m4 = mf4[gw];
                    vm = (m4.x != 0.0f ? 1u : 0u) | (m4.y != 0.0f ? 2u : 0u)
                       | (m4.z != 0.0f ? 4u : 0u) | (m4.w != 0.0f ? 8u : 0u);
                } else if (m_off) {
                    unsigned m4 = mu[gw];
                    vm = ((m4 & 0x000000FFu) ? 1u : 0u) | ((m4 & 0x0000FF00u) ? 2u : 0u)
                       | ((m4 & 0x00FF0000u) ? 4u : 0u) | ((m4 & 0xFF000000u) ? 8u : 0u);
                } else {
                    int4 m4 = mi4[gw];
                    vm = (m4.x ? 1u : 0u) | (m4.y ? 2u : 0u)
                       | (m4.z ? 4u : 0u) | (m4.w ? 8u : 0u);
                }
                unsigned b0 = (unsigned)(s4.x & 127) | ((vm & 1u) << 7);
                unsigned b1 = (unsigned)(s4.y & 127) | ((vm & 2u) << 6);
                unsigned b2 = (unsigned)(s4.z & 127) | ((vm & 4u) << 5);
                unsigned b3 = (unsigned)(s4.w & 127) | ((vm & 8u) << 4);
                mword = b0 | (b1 << 8) | (b2 << 16) | (b3 << 24);
            } else {
                mword = 0;
                for (int b = 0; b < 4; b++) {
                    size_t t = gt + b;
                    if (t < (size_t)n) {
                        int valid;
                        if (m_gt1)      valid = (((const float*)mask)[t] != 0.0f);
                        else if (m_off) valid = (((const unsigned char*)mask)[t] != 0);
                        else            valid = (((const int*)mask)[t] != 0);
                        mword |= ((unsigned)(seg[t] & 127) | ((unsigned)valid << 7)) << (8 * b);
                    }
                }
            }
            s_meta[i] = mword;
        }
    }
    __syncthreads();

    // ---- Phase 2: tile loop — softmax in-place in ring, owner-accumulate. ----
    const unsigned char* metab = (const unsigned char*)s_meta;
    float4 s0 = {0,0,0,0}, s1 = {0,0,0,0}, s2 = {0,0,0,0}, s3 = {0,0,0,0};
    float q0 = 0.f, q1 = 0.f, q2 = 0.f, q3 = 0.f;
    int   n0 = 0, n1 = 0, n2 = 0, n3 = 0;
    unsigned key = 0x20u | (unsigned)warp;      // (meta_byte>>2) for my 4 cols

    for (int t = 0; t < ntiles; t++) {
        int r = t % NSTAGE;
        unsigned ph = (unsigned)((t / NSTAGE) & 1);
        mbar_wait(mb_base + r * 8, ph);

        float4* P4 = (float4*)(ring + r * (TILE_B / 4));
        int tb = t * TILE_T;

        // -- Softmax in place: warp handles tokens {warp + 32j}. --
        unsigned vmask = 0;
        float4 v[4];
        #pragma unroll
        for (int j = 0; j < 4; j++) {
            int tt = warp + 32 * j;
            if (metab[tb + tt] & 0x80u) {
                vmask |= (1u << j);
                v[j] = P4[tt * 32 + lane];
            }
        }
        float z[4];
        #pragma unroll
        for (int j = 0; j < 4; j++) {
            if (vmask & (1u << j)) {
                v[j].x = __expf(v[j].x);
                v[j].y = __expf(v[j].y);
                v[j].z = __expf(v[j].z);
                v[j].w = __expf(v[j].w);
                z[j] = (v[j].x + v[j].y) + (v[j].z + v[j].w);
            } else z[j] = 1.f;
        }
        #pragma unroll
        for (int off = 16; off; off >>= 1) {
            #pragma unroll
            for (int j = 0; j < 4; j++)
                z[j] += __shfl_xor_sync(0xffffffffu, z[j], off);
        }
        #pragma unroll
        for (int j = 0; j < 4; j++) {
            if (vmask & (1u << j)) {
                float rcp = __fdividef(1.0f, z[j]);
                float4 p;
                p.x = v[j].x * rcp; p.y = v[j].y * rcp;
                p.z = v[j].z * rcp; p.w = v[j].w * rcp;
                P4[(warp + 32 * j) * 32 + lane] = p;
            }
        }
        __syncthreads();

        // -- Owner-accumulate: pull rows of my 4 columns from this tile. --
        unsigned word = s_meta[(tb >> 2) + lane];   // lane's 4 tokens of tile
        unsigned my = 0;
        #pragma unroll
        for (int b = 0; b < 4; b++)
            my |= (((word >> (8 * b)) & 0xFFu) >> 2 == key) ? 1u : 0u;
        unsigned bal = __ballot_sync(0xffffffffu, my);
        while (bal) {
            int src = __ffs(bal) - 1;
            bal &= bal - 1;
            unsigned mw = __shfl_sync(0xffffffffu, word, src);
            int base = src * 4;
            #pragma unroll
            for (int b = 0; b < 4; b++) {
                unsigned byte = (mw >> (8 * b)) & 0xFFu;
                if ((byte >> 2) == key) {                 // valid & my column
                    int kk = byte & 3;                    // warp-uniform
                    float4 pv = P4[(base + b) * 32 + lane];
                    float dq = pv.x*pv.x + pv.y*pv.y + pv.z*pv.z + pv.w*pv.w;
                    if (kk == 0)      { s0.x+=pv.x; s0.y+=pv.y; s0.z+=pv.z; s0.w+=pv.w; q0+=dq; n0++; }
                    else if (kk == 1) { s1.x+=pv.x; s1.y+=pv.y; s1.z+=pv.z; s1.w+=pv.w; q1+=dq; n1++; }
                    else if (kk == 2) { s2.x+=pv.x; s2.y+=pv.y; s2.z+=pv.z; s2.w+=pv.w; q2+=dq; n2++; }
                    else              { s3.x+=pv.x; s3.y+=pv.y; s3.z+=pv.z; s3.w+=pv.w; q3+=dq; n3++; }
                }
            }
        }
        __syncthreads();   // stage r free

        // -- Refill stage r for tile t+NSTAGE. --
        if (tid == 0 && t + NSTAGE < ntiles) {
            int tn = t + NSTAGE;
            long long gtok = (long long)start + (long long)tn * TILE_T;
            long long rows = (long long)n - gtok;
            if (rows > TILE_T) rows = TILE_T;
            if (rows > 0) {
                unsigned bytes = (unsigned)rows * 512u;
                mbar_expect_tx(mb_base + r * 8, bytes);
                const char* srcp = (const char*)logits + gtok * 512;
                for (unsigned off = 0; off < bytes; off += CHUNK) {
                    unsigned sz = bytes - off; if (sz > CHUNK) sz = CHUNK;
                    bulk_cp(rg_base + r * TILE_B + off, srcp + off, sz, mb_base + r * 8);
                }
            } else {
                mbar_expect_tx(mb_base + r * 8, 0);
            }
        }
    }

    // ---- Phase 3: write per-CTA partials (coalesced). ----
    {
        int c0 = 4 * warp;
        ((float4*)&g_S[((size_t)(c0 + 0) * NCTA + bid) * C_DIM])[lane] = s0;
        ((float4*)&g_S[((size_t)(c0 + 1) * NCTA + bid) * C_DIM])[lane] = s1;
        ((float4*)&g_S[((size_t)(c0 + 2) * NCTA + bid) * C_DIM])[lane] = s2;
        ((float4*)&g_S[((size_t)(c0 + 3) * NCTA + bid) * C_DIM])[lane] = s3;
        float qs0 = warp_sum(q0), qs1 = warp_sum(q1);
        float qs2 = warp_sum(q2), qs3 = warp_sum(q3);
        if (lane == 0) {
            g_Q[(c0 + 0) * NCTA + bid] = qs0;  g_N[(c0 + 0) * NCTA + bid] = (float)n0;
            g_Q[(c0 + 1) * NCTA + bid] = qs1;  g_N[(c0 + 1) * NCTA + bid] = (float)n1;
            g_Q[(c0 + 2) * NCTA + bid] = qs2;  g_N[(c0 + 2) * NCTA + bid] = (float)n2;
            g_Q[(c0 + 3) * NCTA + bid] = qs3;  g_N[(c0 + 3) * NCTA + bid] = (float)n3;
        }
    }

    // ---- Grid barrier (128 CTAs co-resident). ----
    __syncthreads();
    if (tid == 0) {
        __threadfence();
        atomicAdd(&g_bar, 1u);
        while (*((volatile unsigned*)&g_bar) < (unsigned)NCTA) __nanosleep(32);
        __threadfence();
    }
    __syncthreads();

    // ---- Phase 4: CTA c reduces its contiguous partials. ----
    {
        const float* Sc = g_S + (size_t)c * NCTA * C_DIM;
        int d  = tid & 127;
        int gg = tid >> 7;                      // 8 groups of 16 CTAs
        float sum = 0.f;
        #pragma unroll 4
        for (int j = 0; j < NCTA / 8; j++)
            sum += Sc[(size_t)(gg * (NCTA / 8) + j) * C_DIM + d];
        s_part[gg * C_DIM + d] = sum;
    }
    __syncthreads();

    float v2n = 0.f, qv = 0.f, nv = 0.f;
    if (tid < C_DIM) {
        float sd = 0.f;
        #pragma unroll
        for (int g = 0; g < 8; g++) sd += s_part[g * C_DIM + tid];
        v2n = sd * sd;
        qv = g_Q[c * NCTA + tid];
        nv = g_N[c * NCTA + tid];
    }
    v2n = warp_sum(v2n); qv = warp_sum(qv); nv = warp_sum(nv);
    if (tid < C_DIM && lane == 0) { s_red[warp] = v2n; s_redq[warp] = qv; s_redn[warp] = nv; }
    __syncthreads();

    if (tid == 0) {
        float snorm2 = (s_red[0] + s_red[1]) + (s_red[2] + s_red[3]);
        float q      = (s_redq[0] + s_redq[1]) + (s_redq[2] + s_redq[3]);
        float fn     = (s_redn[0] + s_redn[1]) + (s_redn[2] + s_redn[3]);
        if (fn > 1.0f) {
            float var = (q - snorm2 / fn) / (fn * (float)C_DIM);
            atomicAdd(&g_total, var);
            atomicAdd(&g_cnt, 1);
        }
        __threadfence();
        unsigned d = atomicAdd(&g_done, 1u);
        if (d == (unsigned)(NCTA - 1)) {
            float tot = atomicExch(&g_total, 0.f);
            int   cc  = atomicExch(&g_cnt, 0);
            out[0] = (cc > 0) ? (tot / (float)cc) : 0.f;
            g_bar  = 0u;                        // reset for next graph replay
            atomicExch(&g_done, 0u);
        }
    }
}

extern "C" void kernel_launch(void* const* d_in, const int* in_sizes, int n_in,
                              void* d_out, int out_size) {
    const float* logits = (const float*)d_in[0];
    const int*   seg    = (const int*)d_in[1];
    const void*  mask   = d_in[2];
    int n = in_sizes[1];                 // B*T tokens
    (void)n_in; (void)out_size;

    cudaFuncSetAttribute(fused_kernel,
                         cudaFuncAttributeMaxDynamicSharedMemorySize,
                         NSTAGE * TILE_B);
    fused_kernel<<<NCTA, NTHREADS, NSTAGE * TILE_B>>>(logits, seg, mask,
                                                      (float*)d_out, n);
}